// round 6
// baseline (speedup 1.0000x reference)
#include <cuda_runtime.h>

// Problem constants
#define Nv    20000
#define Tt    32
#define Ee    640000
#define Cc    10
#define Kk    5
#define PADc  2
#define REP   8
#define GSTAT 160
#define GOUT  160

// ---------------- static device scratch (no allocs allowed) ----------------
__device__ int   g_cnt[REP][Nv];    // replicated degree counters
__device__ int   g_cur[REP][Nv];    // replicated scatter cursors
__device__ int   g_row[Nv + 1];     // CSR row offsets
__device__ int   g_adj[Ee];         // CSR adjacency (src per dst)
__device__ float g_invdeg[Nv];
__device__ float g_xn[Nv * Tt];     // normalized x of current layer
__device__ float g_cm[Nv * Tt];     // per-node conv+max message
__device__ float g_x[Nv * Tt];      // layer output buffer
__device__ float g_part[GSTAT * 64];
__device__ float g_mean[Tt];        // alpha * mean (subtract term)
__device__ float g_invn[Tt];        // sqrt(N)/||x - alpha*mean||
__device__ float g_opart[GOUT * 3];

// ---------------- zero counters ----------------
__global__ __launch_bounds__(256) void zero_k() {
    int i = blockIdx.x * blockDim.x + threadIdx.x;
    if (i < REP * Nv) ((int*)g_cnt)[i] = 0;
}

// ---------------- count (8-way replicated to cut atomic contention) --------
__global__ __launch_bounds__(256) void count_k(const int* __restrict__ ei) {
    int e = blockIdx.x * blockDim.x + threadIdx.x;
    if (e < Ee) atomicAdd(&g_cnt[e & 7][ei[Ee + e]], 1);
}

// ---------------- single-block scan: row offsets + per-replica cursor bases --
__global__ __launch_bounds__(512) void scan_k() {
    const int NTH = 512, CH = 40;  // 512*40 = 20480 >= Nv
    int tid = threadIdx.x;
    int base = tid * CH;
    int s = 0;
    for (int i = 0; i < CH; i++) {
        int idx = base + i;
        if (idx < Nv) {
#pragma unroll
            for (int r = 0; r < REP; r++) s += g_cnt[r][idx];
        }
    }
    __shared__ int sh[NTH];
    sh[tid] = s;
    __syncthreads();
    for (int off = 1; off < NTH; off <<= 1) {
        int v = 0;
        if (tid >= off) v = sh[tid - off];
        __syncthreads();
        if (tid >= off) sh[tid] += v;
        __syncthreads();
    }
    int run = sh[tid] - s;  // exclusive prefix of this thread's chunk
    for (int i = 0; i < CH; i++) {
        int idx = base + i;
        if (idx < Nv) {
            int tot = 0;
            int cur = run;
#pragma unroll
            for (int r = 0; r < REP; r++) {
                int c = g_cnt[r][idx];
                g_cur[r][idx] = cur;
                cur += c;
                tot += c;
            }
            g_row[idx] = run;
            g_invdeg[idx] = 1.0f / (float)(tot > 1 ? tot : 1);
            run += tot;
        }
    }
    if (tid == NTH - 1) g_row[Nv] = sh[NTH - 1];
}

// ---------------- scatter (replicated cursors) ----------------
__global__ __launch_bounds__(256) void scatter_k(const int* __restrict__ ei) {
    int e = blockIdx.x * blockDim.x + threadIdx.x;
    if (e < Ee) {
        int d = ei[Ee + e];
        int p = atomicAdd(&g_cur[e & 7][d], 1);
        g_adj[p] = ei[e];
    }
}

// ---------------- per-layer: column stats (deterministic 2-stage) ----------
// use_gx: 0 -> read from external x, 1 -> read from g_x
__global__ __launch_bounds__(256) void stats_k(const float* __restrict__ x, int use_gx) {
    const float* __restrict__ src = use_gx ? (const float*)g_x : x;
    int lane = threadIdx.x & 31;
    int w = threadIdx.x >> 5;  // 0..7
    int wg = blockIdx.x * 8 + w;
    float s = 0.f, q = 0.f;
    for (int n = wg; n < Nv; n += GSTAT * 8) {
        float v = src[n * Tt + lane];
        s += v;
        q = fmaf(v, v, q);
    }
    __shared__ float sh[8][64];
    sh[w][lane] = s;
    sh[w][32 + lane] = q;
    __syncthreads();
    if (w == 0) {
        float ss = 0.f, qq = 0.f;
#pragma unroll
        for (int i = 0; i < 8; i++) { ss += sh[i][lane]; qq += sh[i][32 + lane]; }
        g_part[blockIdx.x * 64 + lane] = ss;
        g_part[blockIdx.x * 64 + 32 + lane] = qq;
    }
}

__global__ __launch_bounds__(32) void stats_fin_k(const float* __restrict__ alpha) {
    int t = threadIdx.x;
    if (t >= Tt) return;
    float s = 0.f, q = 0.f;
    for (int b = 0; b < GSTAT; b++) {
        s += g_part[b * 64 + t];
        q += g_part[b * 64 + 32 + t];
    }
    float m = s / (float)Nv;
    float a = alpha[t];
    // ||x - a*m||^2 = q + N*m^2*(a^2 - 2a)
    float nsq = q + (float)Nv * m * m * (a * a - 2.f * a);
    g_mean[t] = a * m;
    g_invn[t] = sqrtf((float)Nv) * rsqrtf(nsq);
}

// ---------------- per-layer: normalize + per-node conv/max ----------------
// warp per node, lane = temporal index t
__global__ __launch_bounds__(256) void normconv_k(const float* __restrict__ x, int use_gx,
                           const float* __restrict__ Wc,  // [C*K] this layer
                           const float* __restrict__ bc,  // [C]
                           const float* __restrict__ scale,
                           const float* __restrict__ shift) {
    const float* __restrict__ src = use_gx ? (const float*)g_x : x;
    int lane = threadIdx.x & 31;
    int node = (blockIdx.x * blockDim.x + threadIdx.x) >> 5;
    if (node >= Nv) return;

    float v = src[node * Tt + lane];
    v = fmaf((v - g_mean[lane]) * g_invn[lane], scale[lane], shift[lane]);
    g_xn[node * Tt + lane] = v;

    float win[Kk];
#pragma unroll
    for (int d = -PADc; d <= PADc; d++) {
        int si = lane + d;
        float u = __shfl_sync(0xffffffffu, v, si & 31);
        win[d + PADc] = (si >= 0 && si < Tt) ? u : 0.f;
    }

    float mx = -3.0e38f;
#pragma unroll
    for (int c = 0; c < Cc; c++) {
        float a = bc[c];
#pragma unroll
        for (int k = 0; k < Kk; k++) a = fmaf(win[k], Wc[c * Kk + k], a);
        mx = fmaxf(mx, a);
    }
    g_cm[node * Tt + lane] = mx;
}

// ---------------- per-layer: gather-aggregate + update + ReLU -------------
// warp per node, lane = temporal index t; neighbor ids broadcast via shfl
__global__ __launch_bounds__(256) void aggr_k() {
    int lane = threadIdx.x & 31;
    int node = (blockIdx.x * blockDim.x + threadIdx.x) >> 5;
    if (node >= Nv) return;

    int beg = g_row[node];
    int end = g_row[node + 1];
    float acc = 0.f;
    for (int i = beg; i < end; i += 32) {
        int id = (i + lane < end) ? g_adj[i + lane] : 0;
        int m = end - i;
        if (m > 32) m = 32;
        for (int j = 0; j < m; j++) {
            int s = __shfl_sync(0xffffffffu, id, j);
            acc += g_cm[s * Tt + lane];
        }
    }
    float aggr = acc * g_invdeg[node];
    float v = 0.5f * (g_xn[node * Tt + lane] + aggr);
    g_x[node * Tt + lane] = fmaxf(v, 0.f);
}

// ---------------- output head: out = Wout @ rowsum(x) + bout --------------
__global__ __launch_bounds__(256) void outpart_k(const float* __restrict__ Wout) {
    int tid = threadIdx.x;
    float p0 = 0.f, p1 = 0.f, p2 = 0.f;
    for (int n = blockIdx.x * blockDim.x + tid; n < Nv; n += GOUT * 256) {
        const float4* r = (const float4*)(g_x + n * Tt);
        float s = 0.f;
#pragma unroll
        for (int i = 0; i < 8; i++) {
            float4 f = r[i];
            s += (f.x + f.y) + (f.z + f.w);
        }
        p0 = fmaf(Wout[n], s, p0);
        p1 = fmaf(Wout[Nv + n], s, p1);
        p2 = fmaf(Wout[2 * Nv + n], s, p2);
    }
    __shared__ float sh0[256], sh1[256], sh2[256];
    sh0[tid] = p0; sh1[tid] = p1; sh2[tid] = p2;
    __syncthreads();
    for (int off = 128; off > 0; off >>= 1) {
        if (tid < off) {
            sh0[tid] += sh0[tid + off];
            sh1[tid] += sh1[tid + off];
            sh2[tid] += sh2[tid + off];
        }
        __syncthreads();
    }
    if (tid == 0) {
        g_opart[blockIdx.x * 3 + 0] = sh0[0];
        g_opart[blockIdx.x * 3 + 1] = sh1[0];
        g_opart[blockIdx.x * 3 + 2] = sh2[0];
    }
}

__global__ __launch_bounds__(32) void outfin_k(const float* __restrict__ bout,
                                               float* __restrict__ out) {
    int j = threadIdx.x;
    if (j < 3) {
        float s = bout[j];
        for (int b = 0; b < GOUT; b++) s += g_opart[b * 3 + j];
        out[j] = s;
    }
}

// ---------------- launch ---------------------------------------------------
extern "C" void kernel_launch(void* const* d_in, const int* in_sizes, int n_in,
                              void* d_out, int out_size) {
    const float* x     = (const float*)d_in[0];  // [N,T]
    const float* convW = (const float*)d_in[1];  // [L,C,1,K]
    const float* convb = (const float*)d_in[2];  // [L,C]
    const float* alpha = (const float*)d_in[3];  // [L,T]
    const float* scale = (const float*)d_in[4];  // [L,T]
    const float* shift = (const float*)d_in[5];  // [L,T]
    const float* Wout  = (const float*)d_in[6];  // [3,N]
    const float* bout  = (const float*)d_in[7];  // [3]
    const int*   ei    = (const int*)d_in[8];    // [2,E]
    float* out = (float*)d_out;

    // CSR build (rebuilt every replay; atomics mutate counters/cursors)
    zero_k<<<(REP * Nv + 255) / 256, 256>>>();
    count_k<<<(Ee + 255) / 256, 256>>>(ei);
    scan_k<<<1, 512>>>();
    scatter_k<<<(Ee + 255) / 256, 256>>>(ei);

    const int nodeBlocks = (Nv + 7) / 8;  // warp per node, 8 warps/block

    for (int l = 0; l < 2; l++) {
        int use_gx = (l > 0) ? 1 : 0;
        stats_k<<<GSTAT, 256>>>(x, use_gx);
        stats_fin_k<<<1, 32>>>(alpha + l * Tt);
        normconv_k<<<nodeBlocks, 256>>>(x, use_gx,
                                        convW + l * Cc * Kk,
                                        convb + l * Cc,
                                        scale + l * Tt,
                                        shift + l * Tt);
        aggr_k<<<nodeBlocks, 256>>>();
    }

    outpart_k<<<GOUT, 256>>>(Wout);
    outfin_k<<<1, 32>>>(bout, out);
}

// round 7
// speedup vs baseline: 3.6516x; 3.6516x over previous
#include <cuda_runtime.h>

// Problem constants
#define Nv    20000
#define Tt    32
#define Ee    640000
#define Cc    10
#define Kk    5
#define PADc  2
#define REP   8
#define MAXG  512
#define NTH   256

// ---------------- static device scratch (no allocs allowed) ----------------
__device__ int   g_cnt[REP][Nv];    // replicated degree counters
__device__ int   g_cur[REP][Nv];    // replicated scatter cursors
__device__ int   g_row[Nv + 1];     // CSR row offsets
__device__ int   g_adj[Ee];         // CSR adjacency (src per dst)
__device__ float g_invdeg[Nv];
__device__ float g_xn[Nv * Tt];     // normalized x of current layer
__device__ float g_cm[Nv * Tt];     // per-node conv+max message
__device__ float g_x[Nv * Tt];      // layer-0 output
__device__ int   g_bsum[MAXG];      // per-block chunk degree sums
__device__ float g_stat0[64];       // layer-0 sum / sumsq per t
__device__ float g_stat1[64];       // layer-1 sum / sumsq per t
__device__ float g_out3[3];         // output partial sums

// -------- device-wide barrier: monotonic epoch, self-resetting arrive ------
__device__ unsigned g_bar_arrive;          // zero-init; reset by last arriver
__device__ volatile unsigned g_bar_epoch;  // monotonic across replays

__device__ __forceinline__ void gsync() {
    __syncthreads();
    if (threadIdx.x == 0) {
        __threadfence();
        unsigned e = g_bar_epoch;
        if (atomicAdd(&g_bar_arrive, 1u) == gridDim.x - 1u) {
            g_bar_arrive = 0u;
            __threadfence();
            g_bar_epoch = e + 1u;
        } else {
            while (g_bar_epoch == e) { __nanosleep(64); }
        }
        __threadfence();
    }
    __syncthreads();
}

// ---------------- the whole model as one persistent kernel ----------------
__global__ void __launch_bounds__(NTH) sage_fused(
    const float* __restrict__ x,     // [N,T]
    const float* __restrict__ convW, // [L,C,1,K]
    const float* __restrict__ convb, // [L,C]
    const float* __restrict__ alpha, // [L,T]
    const float* __restrict__ scale, // [L,T]
    const float* __restrict__ shift, // [L,T]
    const float* __restrict__ Wout,  // [3,N]
    const float* __restrict__ bout,  // [3]
    const int*   __restrict__ ei,    // [2,E]
    float*       __restrict__ out)   // [3]
{
    const int tid  = threadIdx.x;
    const int lane = tid & 31;
    const int w    = tid >> 5;
    const int b    = blockIdx.x;
    const int G    = gridDim.x;
    const int nthreads = G * NTH;
    const int gtid     = b * NTH + tid;
    const int nwarps   = G * 8;
    const int gwarp    = b * 8 + w;

    __shared__ int   sA[512], sB[512];
    __shared__ int   sc[256];
    __shared__ float sh[8][64];
    __shared__ float sm[Tt], smul[Tt], ssh[Tt];
    __shared__ float sW[Cc * Kk];
    __shared__ float sbias[Cc];
    __shared__ float shp[8][3];

    // ---- P0: zero counters + stat accumulators ----
    for (int i = gtid; i < REP * Nv; i += nthreads) ((int*)g_cnt)[i] = 0;
    if (b == 0) {
        if (tid < 64) { g_stat0[tid] = 0.f; g_stat1[tid] = 0.f; }
        if (tid < 3)  g_out3[tid] = 0.f;
    }
    gsync();  // S1

    // ---- P1: degree count (replicated atomics) + layer-0 column stats ----
    for (int e = gtid; e < Ee; e += nthreads)
        atomicAdd(&g_cnt[e & (REP - 1)][ei[Ee + e]], 1);
    {
        const int GSB = (G < 128) ? G : 128;
        if (b < GSB) {
            float s = 0.f, q = 0.f;
            for (int n = b * 8 + w; n < Nv; n += GSB * 8) {
                float v = x[n * Tt + lane];
                s += v; q = fmaf(v, v, q);
            }
            sh[w][lane] = s; sh[w][32 + lane] = q;
            __syncthreads();
            if (tid < 64) {
                float v = 0.f;
#pragma unroll
                for (int i = 0; i < 8; i++) v += sh[i][tid];
                atomicAdd(&g_stat0[tid], v);
            }
        }
    }
    gsync();  // S2

    // ---- P2: scanA — per-block chunk degree sums ----
    const int CH = (Nv + G - 1) / G;  // <= 256 for G >= 79
    int mytot = 0;
    const int myidx = b * CH + tid;
    if (tid < CH && myidx < Nv) {
#pragma unroll
        for (int r = 0; r < REP; r++) mytot += g_cnt[r][myidx];
    }
    sc[tid] = (tid < CH) ? mytot : 0;
    __syncthreads();
    sA[tid] = sc[tid];
    __syncthreads();
    for (int off = 128; off > 0; off >>= 1) {
        if (tid < off) sA[tid] += sA[tid + off];
        __syncthreads();
    }
    if (tid == 0) g_bsum[b] = sA[0];
    gsync();  // S3

    // ---- P3: redundant global scan of block sums + local scan -> CSR ----
    {
        sA[tid]       = (tid < G) ? g_bsum[tid] : 0;
        sA[tid + 256] = (tid + 256 < G) ? g_bsum[tid + 256] : 0;
        __syncthreads();
        int* src = sA; int* dst = sB;
        for (int off = 1; off < 512; off <<= 1) {
            int i0 = tid, i1 = tid + 256;
            int v0 = src[i0] + ((i0 >= off) ? src[i0 - off] : 0);
            int v1 = src[i1] + ((i1 >= off) ? src[i1 - off] : 0);
            dst[i0] = v0; dst[i1] = v1;
            __syncthreads();
            int* t = src; src = dst; dst = t;
        }
        int base = (b == 0) ? 0 : src[b - 1];  // exclusive prefix of this block
        __syncthreads();
        // local inclusive scan of sc[0..255]
        int* ls = sA; int* ld_ = sB;
        ls[tid] = sc[tid];
        __syncthreads();
        for (int off = 1; off < 256; off <<= 1) {
            int v = ls[tid] + ((tid >= off) ? ls[tid - off] : 0);
            ld_[tid] = v;
            __syncthreads();
            int* t = ls; ls = ld_; ld_ = t;
        }
        if (tid < CH && myidx < Nv) {
            int run = base + ls[tid] - mytot;  // exclusive
            g_row[myidx] = run;
            int cur = run;
#pragma unroll
            for (int r = 0; r < REP; r++) {
                g_cur[r][myidx] = cur;
                cur += g_cnt[r][myidx];
            }
            g_invdeg[myidx] = 1.0f / (float)(mytot > 1 ? mytot : 1);
            if (myidx == Nv - 1) g_row[Nv] = run + mytot;
        }
    }
    gsync();  // S4

    // ---- P4: scatter + layer-0 stats finish + normconv-0 ----
    for (int e = gtid; e < Ee; e += nthreads) {
        int d = ei[Ee + e];
        int p = atomicAdd(&g_cur[e & (REP - 1)][d], 1);
        g_adj[p] = ei[e];
    }
    if (tid < Tt) {
        float s = g_stat0[tid], q = g_stat0[32 + tid];
        float m = s / (float)Nv;
        float a = alpha[tid];
        float nsq = q + (float)Nv * m * m * (a * a - 2.f * a);
        float invn = sqrtf((float)Nv) * rsqrtf(nsq);
        sm[tid]   = a * m;
        smul[tid] = invn * scale[tid];
        ssh[tid]  = shift[tid];
    }
    if (tid < Cc * Kk) sW[tid] = convW[tid];
    if (tid < Cc)      sbias[tid] = convb[tid];
    __syncthreads();
    for (int node = gwarp; node < Nv; node += nwarps) {
        float v = x[node * Tt + lane];
        v = fmaf(v - sm[lane], smul[lane], ssh[lane]);
        g_xn[node * Tt + lane] = v;
        float win[Kk];
#pragma unroll
        for (int d = -PADc; d <= PADc; d++) {
            int si = lane + d;
            float u = __shfl_sync(0xffffffffu, v, si & 31);
            win[d + PADc] = (si >= 0 && si < Tt) ? u : 0.f;
        }
        float mx = -3.0e38f;
#pragma unroll
        for (int c = 0; c < Cc; c++) {
            float a2 = sbias[c];
#pragma unroll
            for (int k = 0; k < Kk; k++) a2 = fmaf(win[k], sW[c * Kk + k], a2);
            mx = fmaxf(mx, a2);
        }
        g_cm[node * Tt + lane] = mx;
    }
    gsync();  // S5

    // ---- P5: aggr-0 (+relu) -> g_x, fused layer-1 stats accumulation ----
    {
        float s = 0.f, q = 0.f;
        for (int node = gwarp; node < Nv; node += nwarps) {
            int beg = g_row[node], end = g_row[node + 1];
            float a0 = 0.f, a1 = 0.f, a2 = 0.f, a3 = 0.f;
            int i = beg;
            for (; i + 32 <= end; i += 32) {
                int id = g_adj[i + lane];
#pragma unroll
                for (int j = 0; j < 32; j += 4) {
                    int s0 = __shfl_sync(0xffffffffu, id, j);
                    int s1 = __shfl_sync(0xffffffffu, id, j + 1);
                    int s2 = __shfl_sync(0xffffffffu, id, j + 2);
                    int s3 = __shfl_sync(0xffffffffu, id, j + 3);
                    a0 += g_cm[s0 * Tt + lane];
                    a1 += g_cm[s1 * Tt + lane];
                    a2 += g_cm[s2 * Tt + lane];
                    a3 += g_cm[s3 * Tt + lane];
                }
            }
            if (i < end) {
                int id = (i + lane < end) ? g_adj[i + lane] : 0;
                int m = end - i;
                for (int j = 0; j < m; j++) {
                    int s0 = __shfl_sync(0xffffffffu, id, j);
                    a0 += g_cm[s0 * Tt + lane];
                }
            }
            float acc = (a0 + a1) + (a2 + a3);
            float v = fmaxf(0.5f * (g_xn[node * Tt + lane] + acc * g_invdeg[node]), 0.f);
            g_x[node * Tt + lane] = v;
            s += v; q = fmaf(v, v, q);
        }
        sh[w][lane] = s; sh[w][32 + lane] = q;
        __syncthreads();
        if (tid < 64) {
            float v = 0.f;
#pragma unroll
            for (int i = 0; i < 8; i++) v += sh[i][tid];
            atomicAdd(&g_stat1[tid], v);
        }
    }
    gsync();  // S6

    // ---- P6: layer-1 stats finish + normconv-1 (src = g_x) ----
    if (tid < Tt) {
        float s = g_stat1[tid], q = g_stat1[32 + tid];
        float m = s / (float)Nv;
        float a = alpha[Tt + tid];
        float nsq = q + (float)Nv * m * m * (a * a - 2.f * a);
        float invn = sqrtf((float)Nv) * rsqrtf(nsq);
        sm[tid]   = a * m;
        smul[tid] = invn * scale[Tt + tid];
        ssh[tid]  = shift[Tt + tid];
    }
    if (tid < Cc * Kk) sW[tid] = convW[Cc * Kk + tid];
    if (tid < Cc)      sbias[tid] = convb[Cc + tid];
    __syncthreads();
    for (int node = gwarp; node < Nv; node += nwarps) {
        float v = g_x[node * Tt + lane];
        v = fmaf(v - sm[lane], smul[lane], ssh[lane]);
        g_xn[node * Tt + lane] = v;
        float win[Kk];
#pragma unroll
        for (int d = -PADc; d <= PADc; d++) {
            int si = lane + d;
            float u = __shfl_sync(0xffffffffu, v, si & 31);
            win[d + PADc] = (si >= 0 && si < Tt) ? u : 0.f;
        }
        float mx = -3.0e38f;
#pragma unroll
        for (int c = 0; c < Cc; c++) {
            float a2 = sbias[c];
#pragma unroll
            for (int k = 0; k < Kk; k++) a2 = fmaf(win[k], sW[c * Kk + k], a2);
            mx = fmaxf(mx, a2);
        }
        g_cm[node * Tt + lane] = mx;
    }
    gsync();  // S7

    // ---- P7: aggr-1 (+relu) fused with output head partials ----
    {
        float p0 = 0.f, p1 = 0.f, p2 = 0.f;
        for (int node = gwarp; node < Nv; node += nwarps) {
            int beg = g_row[node], end = g_row[node + 1];
            float a0 = 0.f, a1 = 0.f, a2 = 0.f, a3 = 0.f;
            int i = beg;
            for (; i + 32 <= end; i += 32) {
                int id = g_adj[i + lane];
#pragma unroll
                for (int j = 0; j < 32; j += 4) {
                    int s0 = __shfl_sync(0xffffffffu, id, j);
                    int s1 = __shfl_sync(0xffffffffu, id, j + 1);
                    int s2 = __shfl_sync(0xffffffffu, id, j + 2);
                    int s3 = __shfl_sync(0xffffffffu, id, j + 3);
                    a0 += g_cm[s0 * Tt + lane];
                    a1 += g_cm[s1 * Tt + lane];
                    a2 += g_cm[s2 * Tt + lane];
                    a3 += g_cm[s3 * Tt + lane];
                }
            }
            if (i < end) {
                int id = (i + lane < end) ? g_adj[i + lane] : 0;
                int m = end - i;
                for (int j = 0; j < m; j++) {
                    int s0 = __shfl_sync(0xffffffffu, id, j);
                    a0 += g_cm[s0 * Tt + lane];
                }
            }
            float acc = (a0 + a1) + (a2 + a3);
            float v = fmaxf(0.5f * (g_xn[node * Tt + lane] + acc * g_invdeg[node]), 0.f);
            float srow = v;
#pragma unroll
            for (int off = 16; off > 0; off >>= 1)
                srow += __shfl_down_sync(0xffffffffu, srow, off);
            if (lane == 0) {
                p0 = fmaf(Wout[node], srow, p0);
                p1 = fmaf(Wout[Nv + node], srow, p1);
                p2 = fmaf(Wout[2 * Nv + node], srow, p2);
            }
        }
        if (lane == 0) { shp[w][0] = p0; shp[w][1] = p1; shp[w][2] = p2; }
        __syncthreads();
        if (tid < 3) {
            float v = 0.f;
#pragma unroll
            for (int i = 0; i < 8; i++) v += shp[i][tid];
            atomicAdd(&g_out3[tid], v);
        }
    }
    gsync();  // S8

    // ---- P8: write the 3 logits ----
    if (b == 0 && tid < 3) out[tid] = g_out3[tid] + bout[tid];
}

// ---------------- launch ---------------------------------------------------
extern "C" void kernel_launch(void* const* d_in, const int* in_sizes, int n_in,
                              void* d_out, int out_size) {
    const float* x     = (const float*)d_in[0];
    const float* convW = (const float*)d_in[1];
    const float* convb = (const float*)d_in[2];
    const float* alpha = (const float*)d_in[3];
    const float* scale = (const float*)d_in[4];
    const float* shift = (const float*)d_in[5];
    const float* Wout  = (const float*)d_in[6];
    const float* bout  = (const float*)d_in[7];
    const int*   ei    = (const int*)d_in[8];
    float*       out   = (float*)d_out;

    int dev = 0;
    cudaGetDevice(&dev);
    int sms = 0;
    cudaDeviceGetAttribute(&sms, cudaDevAttrMultiProcessorCount, dev);
    int bpm = 0;
    cudaOccupancyMaxActiveBlocksPerMultiprocessor(&bpm, sage_fused, NTH, 0);
    if (bpm < 1) bpm = 1;
    int G = sms * bpm;
    if (G > MAXG) G = MAXG;

    void* args[10] = {
        (void*)&x, (void*)&convW, (void*)&convb, (void*)&alpha, (void*)&scale,
        (void*)&shift, (void*)&Wout, (void*)&bout, (void*)&ei, (void*)&out
    };
    cudaLaunchCooperativeKernel((const void*)sage_fused, dim3(G), dim3(NTH),
                                args, 0, (cudaStream_t)0);
}

// round 8
// speedup vs baseline: 4.0750x; 1.1160x over previous
#include <cuda_runtime.h>

// Problem constants
#define Nv    20000
#define Tt    32
#define Ee    640000
#define Cc    10
#define Kk    5
#define PADc  2
#define REP   8
#define MAXG  512
#define NTH   256

// ---------------- static device scratch (no allocs allowed) ----------------
__device__ int   g_cnt[REP][Nv];    // replicated degree counters
__device__ int   g_cur[REP][Nv];    // replicated scatter cursors
__device__ int   g_row[Nv + 1];     // CSR row offsets
__device__ int   g_adj[Ee];         // CSR adjacency (src per dst)
__device__ float g_invdeg[Nv];
__device__ float g_xn[Nv * Tt];     // normalized x of current layer
__device__ float g_cm[Nv * Tt];     // per-node conv+max message
__device__ float g_x[Nv * Tt];      // layer-0 output
__device__ int   g_bsum[MAXG];      // per-block chunk degree sums
__device__ float g_stat0[64];       // layer-0 sum / sumsq per t
__device__ float g_stat1[64];       // layer-1 sum / sumsq per t
__device__ float g_out3[3];         // output partial sums

// -------- device-wide barrier: monotonic epoch, self-resetting arrive ------
__device__ unsigned g_bar_arrive;          // zero-init; reset by last arriver
__device__ volatile unsigned g_bar_epoch;  // monotonic across replays

__device__ __forceinline__ void gsync() {
    __syncthreads();
    if (threadIdx.x == 0) {
        __threadfence();
        unsigned e = g_bar_epoch;
        if (atomicAdd(&g_bar_arrive, 1u) == gridDim.x - 1u) {
            g_bar_arrive = 0u;
            __threadfence();
            g_bar_epoch = e + 1u;
        } else {
            while (g_bar_epoch == e) { __nanosleep(64); }
        }
        __threadfence();
    }
    __syncthreads();
}

// ---------------- the whole model as one persistent kernel ----------------
__global__ void __launch_bounds__(NTH, 4) sage_fused(
    const float* __restrict__ x,     // [N,T]
    const float* __restrict__ convW, // [L,C,1,K]
    const float* __restrict__ convb, // [L,C]
    const float* __restrict__ alpha, // [L,T]
    const float* __restrict__ scale, // [L,T]
    const float* __restrict__ shift, // [L,T]
    const float* __restrict__ Wout,  // [3,N]
    const float* __restrict__ bout,  // [3]
    const int*   __restrict__ ei,    // [2,E]
    float*       __restrict__ out)   // [3]
{
    const int tid  = threadIdx.x;
    const int lane = tid & 31;
    const int w    = tid >> 5;
    const int b    = blockIdx.x;
    const int G    = gridDim.x;
    const int nthreads = G * NTH;
    const int gtid     = b * NTH + tid;
    const int nwarps   = G * 8;
    const int gwarp    = b * 8 + w;

    __shared__ int   sA[512], sB[512];
    __shared__ int   sc[256];
    __shared__ float sh[8][64];
    __shared__ float sm[Tt], smul[Tt], ssh[Tt];
    __shared__ float sW[Cc * Kk];
    __shared__ float sbias[Cc];
    __shared__ float shp[8][3];

    // ---- P0: zero counters + stat accumulators ----
    for (int i = gtid; i < REP * Nv; i += nthreads) ((int*)g_cnt)[i] = 0;
    if (b == 0) {
        if (tid < 64) { g_stat0[tid] = 0.f; g_stat1[tid] = 0.f; }
        if (tid < 3)  g_out3[tid] = 0.f;
    }
    gsync();  // S1

    // ---- P1: degree count (replicated atomics) + layer-0 column stats ----
    for (int e = gtid; e < Ee; e += nthreads)
        atomicAdd(&g_cnt[e & (REP - 1)][ei[Ee + e]], 1);
    {
        const int GSB = (G < 128) ? G : 128;
        if (b < GSB) {
            float s = 0.f, q = 0.f;
            for (int n = b * 8 + w; n < Nv; n += GSB * 8) {
                float v = x[n * Tt + lane];
                s += v; q = fmaf(v, v, q);
            }
            sh[w][lane] = s; sh[w][32 + lane] = q;
            __syncthreads();
            if (tid < 64) {
                float v = 0.f;
#pragma unroll
                for (int i = 0; i < 8; i++) v += sh[i][tid];
                atomicAdd(&g_stat0[tid], v);
            }
        }
    }
    gsync();  // S2

    // ---- P2: scanA — per-block chunk degree sums ----
    const int CH = (Nv + G - 1) / G;  // <= 256 for G >= 79
    int mytot = 0;
    const int myidx = b * CH + tid;
    if (tid < CH && myidx < Nv) {
#pragma unroll
        for (int r = 0; r < REP; r++) mytot += g_cnt[r][myidx];
    }
    sc[tid] = (tid < CH) ? mytot : 0;
    __syncthreads();
    sA[tid] = sc[tid];
    __syncthreads();
    for (int off = 128; off > 0; off >>= 1) {
        if (tid < off) sA[tid] += sA[tid + off];
        __syncthreads();
    }
    if (tid == 0) g_bsum[b] = sA[0];
    gsync();  // S3

    // ---- P3: redundant global scan of block sums + local scan -> CSR ----
    {
        sA[tid]       = (tid < G) ? g_bsum[tid] : 0;
        sA[tid + 256] = (tid + 256 < G) ? g_bsum[tid + 256] : 0;
        __syncthreads();
        int* src = sA; int* dst = sB;
        for (int off = 1; off < 512; off <<= 1) {
            int i0 = tid, i1 = tid + 256;
            int v0 = src[i0] + ((i0 >= off) ? src[i0 - off] : 0);
            int v1 = src[i1] + ((i1 >= off) ? src[i1 - off] : 0);
            dst[i0] = v0; dst[i1] = v1;
            __syncthreads();
            int* t = src; src = dst; dst = t;
        }
        int base = (b == 0) ? 0 : src[b - 1];  // exclusive prefix of this block
        __syncthreads();
        // local inclusive scan of sc[0..255]
        int* ls = sA; int* ld_ = sB;
        ls[tid] = sc[tid];
        __syncthreads();
        for (int off = 1; off < 256; off <<= 1) {
            int v = ls[tid] + ((tid >= off) ? ls[tid - off] : 0);
            ld_[tid] = v;
            __syncthreads();
            int* t = ls; ls = ld_; ld_ = t;
        }
        if (tid < CH && myidx < Nv) {
            int run = base + ls[tid] - mytot;  // exclusive
            g_row[myidx] = run;
            int cur = run;
#pragma unroll
            for (int r = 0; r < REP; r++) {
                g_cur[r][myidx] = cur;
                cur += g_cnt[r][myidx];
            }
            g_invdeg[myidx] = 1.0f / (float)(mytot > 1 ? mytot : 1);
            if (myidx == Nv - 1) g_row[Nv] = run + mytot;
        }
    }
    gsync();  // S4

    // ---- P4: scatter + layer-0 stats finish + normconv-0 ----
    for (int e = gtid; e < Ee; e += nthreads) {
        int d = ei[Ee + e];
        int p = atomicAdd(&g_cur[e & (REP - 1)][d], 1);
        g_adj[p] = ei[e];
    }
    if (tid < Tt) {
        float s = g_stat0[tid], q = g_stat0[32 + tid];
        float m = s / (float)Nv;
        float a = alpha[tid];
        float nsq = q + (float)Nv * m * m * (a * a - 2.f * a);
        float invn = sqrtf((float)Nv) * rsqrtf(nsq);
        sm[tid]   = a * m;
        smul[tid] = invn * scale[tid];
        ssh[tid]  = shift[tid];
    }
    if (tid < Cc * Kk) sW[tid] = convW[tid];
    if (tid < Cc)      sbias[tid] = convb[tid];
    __syncthreads();
    for (int node = gwarp; node < Nv; node += nwarps) {
        float v = x[node * Tt + lane];
        v = fmaf(v - sm[lane], smul[lane], ssh[lane]);
        g_xn[node * Tt + lane] = v;
        float win[Kk];
#pragma unroll
        for (int d = -PADc; d <= PADc; d++) {
            int si = lane + d;
            float u = __shfl_sync(0xffffffffu, v, si & 31);
            win[d + PADc] = (si >= 0 && si < Tt) ? u : 0.f;
        }
        float mx = -3.0e38f;
#pragma unroll
        for (int c = 0; c < Cc; c++) {
            float a2 = sbias[c];
#pragma unroll
            for (int k = 0; k < Kk; k++) a2 = fmaf(win[k], sW[c * Kk + k], a2);
            mx = fmaxf(mx, a2);
        }
        g_cm[node * Tt + lane] = mx;
    }
    gsync();  // S5

    // ---- P5: aggr-0 (+relu) -> g_x, fused layer-1 stats accumulation ----
    {
        float s = 0.f, q = 0.f;
        for (int node = gwarp; node < Nv; node += nwarps) {
            int beg = g_row[node], end = g_row[node + 1];
            float a0 = 0.f, a1 = 0.f, a2 = 0.f, a3 = 0.f;
            int i = beg;
            for (; i + 32 <= end; i += 32) {
                int id = g_adj[i + lane];
#pragma unroll
                for (int j = 0; j < 32; j += 4) {
                    int s0 = __shfl_sync(0xffffffffu, id, j);
                    int s1 = __shfl_sync(0xffffffffu, id, j + 1);
                    int s2 = __shfl_sync(0xffffffffu, id, j + 2);
                    int s3 = __shfl_sync(0xffffffffu, id, j + 3);
                    a0 += g_cm[s0 * Tt + lane];
                    a1 += g_cm[s1 * Tt + lane];
                    a2 += g_cm[s2 * Tt + lane];
                    a3 += g_cm[s3 * Tt + lane];
                }
            }
            if (i < end) {
                int id = (i + lane < end) ? g_adj[i + lane] : 0;
                int m = end - i;
                for (int j = 0; j < m; j++) {
                    int s0 = __shfl_sync(0xffffffffu, id, j);
                    a0 += g_cm[s0 * Tt + lane];
                }
            }
            float acc = (a0 + a1) + (a2 + a3);
            float v = fmaxf(0.5f * (g_xn[node * Tt + lane] + acc * g_invdeg[node]), 0.f);
            g_x[node * Tt + lane] = v;
            s += v; q = fmaf(v, v, q);
        }
        sh[w][lane] = s; sh[w][32 + lane] = q;
        __syncthreads();
        if (tid < 64) {
            float v = 0.f;
#pragma unroll
            for (int i = 0; i < 8; i++) v += sh[i][tid];
            atomicAdd(&g_stat1[tid], v);
        }
    }
    gsync();  // S6

    // ---- P6: layer-1 stats finish + normconv-1 (src = g_x) ----
    if (tid < Tt) {
        float s = g_stat1[tid], q = g_stat1[32 + tid];
        float m = s / (float)Nv;
        float a = alpha[Tt + tid];
        float nsq = q + (float)Nv * m * m * (a * a - 2.f * a);
        float invn = sqrtf((float)Nv) * rsqrtf(nsq);
        sm[tid]   = a * m;
        smul[tid] = invn * scale[Tt + tid];
        ssh[tid]  = shift[Tt + tid];
    }
    if (tid < Cc * Kk) sW[tid] = convW[Cc * Kk + tid];
    if (tid < Cc)      sbias[tid] = convb[Cc + tid];
    __syncthreads();
    for (int node = gwarp; node < Nv; node += nwarps) {
        float v = g_x[node * Tt + lane];
        v = fmaf(v - sm[lane], smul[lane], ssh[lane]);
        g_xn[node * Tt + lane] = v;
        float win[Kk];
#pragma unroll
        for (int d = -PADc; d <= PADc; d++) {
            int si = lane + d;
            float u = __shfl_sync(0xffffffffu, v, si & 31);
            win[d + PADc] = (si >= 0 && si < Tt) ? u : 0.f;
        }
        float mx = -3.0e38f;
#pragma unroll
        for (int c = 0; c < Cc; c++) {
            float a2 = sbias[c];
#pragma unroll
            for (int k = 0; k < Kk; k++) a2 = fmaf(win[k], sW[c * Kk + k], a2);
            mx = fmaxf(mx, a2);
        }
        g_cm[node * Tt + lane] = mx;
    }
    gsync();  // S7

    // ---- P7: aggr-1 (+relu) fused with output head partials ----
    {
        float p0 = 0.f, p1 = 0.f, p2 = 0.f;
        for (int node = gwarp; node < Nv; node += nwarps) {
            int beg = g_row[node], end = g_row[node + 1];
            float a0 = 0.f, a1 = 0.f, a2 = 0.f, a3 = 0.f;
            int i = beg;
            for (; i + 32 <= end; i += 32) {
                int id = g_adj[i + lane];
#pragma unroll
                for (int j = 0; j < 32; j += 4) {
                    int s0 = __shfl_sync(0xffffffffu, id, j);
                    int s1 = __shfl_sync(0xffffffffu, id, j + 1);
                    int s2 = __shfl_sync(0xffffffffu, id, j + 2);
                    int s3 = __shfl_sync(0xffffffffu, id, j + 3);
                    a0 += g_cm[s0 * Tt + lane];
                    a1 += g_cm[s1 * Tt + lane];
                    a2 += g_cm[s2 * Tt + lane];
                    a3 += g_cm[s3 * Tt + lane];
                }
            }
            if (i < end) {
                int id = (i + lane < end) ? g_adj[i + lane] : 0;
                int m = end - i;
                for (int j = 0; j < m; j++) {
                    int s0 = __shfl_sync(0xffffffffu, id, j);
                    a0 += g_cm[s0 * Tt + lane];
                }
            }
            float acc = (a0 + a1) + (a2 + a3);
            float v = fmaxf(0.5f * (g_xn[node * Tt + lane] + acc * g_invdeg[node]), 0.f);
            float srow = v;
#pragma unroll
            for (int off = 16; off > 0; off >>= 1)
                srow += __shfl_down_sync(0xffffffffu, srow, off);
            if (lane == 0) {
                p0 = fmaf(Wout[node], srow, p0);
                p1 = fmaf(Wout[Nv + node], srow, p1);
                p2 = fmaf(Wout[2 * Nv + node], srow, p2);
            }
        }
        if (lane == 0) { shp[w][0] = p0; shp[w][1] = p1; shp[w][2] = p2; }
        __syncthreads();
        if (tid < 3) {
            float v = 0.f;
#pragma unroll
            for (int i = 0; i < 8; i++) v += shp[i][tid];
            atomicAdd(&g_out3[tid], v);
        }
    }
    gsync();  // S8

    // ---- P8: write the 3 logits ----
    if (b == 0 && tid < 3) out[tid] = g_out3[tid] + bout[tid];
}

// ---------------- launch ---------------------------------------------------
extern "C" void kernel_launch(void* const* d_in, const int* in_sizes, int n_in,
                              void* d_out, int out_size) {
    const float* x     = (const float*)d_in[0];
    const float* convW = (const float*)d_in[1];
    const float* convb = (const float*)d_in[2];
    const float* alpha = (const float*)d_in[3];
    const float* scale = (const float*)d_in[4];
    const float* shift = (const float*)d_in[5];
    const float* Wout  = (const float*)d_in[6];
    const float* bout  = (const float*)d_in[7];
    const int*   ei    = (const int*)d_in[8];
    float*       out   = (float*)d_out;

    int dev = 0;
    cudaGetDevice(&dev);
    int sms = 0;
    cudaDeviceGetAttribute(&sms, cudaDevAttrMultiProcessorCount, dev);
    int bpm = 0;
    cudaOccupancyMaxActiveBlocksPerMultiprocessor(&bpm, sage_fused, NTH, 0);
    if (bpm < 1) bpm = 1;
    int G = sms * bpm;
    if (G > MAXG) G = MAXG;

    void* args[10] = {
        (void*)&x, (void*)&convW, (void*)&convb, (void*)&alpha, (void*)&scale,
        (void*)&shift, (void*)&Wout, (void*)&bout, (void*)&ei, (void*)&out
    };
    cudaLaunchCooperativeKernel((const void*)sage_fused, dim3(G), dim3(NTH),
                                args, 0, (cudaStream_t)0);
}

// round 9
// speedup vs baseline: 4.5356x; 1.1130x over previous
#include <cuda_runtime.h>

// Problem constants
#define Nv    20000
#define Tt    32
#define Ee    640000
#define Cc    10
#define Kk    5
#define PADc  2
#define CAP   128      // bucket capacity per node (mean deg 32; P(>=128) ~ e^-81)
#define MAXG  512
#define NTH   256

// ---------------- static device scratch (no allocs allowed) ----------------
__device__ int   g_cnt[Nv];         // per-node degree / bucket cursor
__device__ int   g_adj[Nv * CAP];   // bucketed adjacency (src per dst)
__device__ float g_xn[Nv * Tt];     // normalized x of current layer
__device__ float g_cm[Nv * Tt];     // per-node conv+max message
__device__ float g_x[Nv * Tt];      // layer-0 output
__device__ float g_stat0[64];       // layer-0 sum / sumsq per t
__device__ float g_stat1[64];       // layer-1 sum / sumsq per t
__device__ float g_out3[3];         // output partial sums

// -------- device-wide barrier: monotonic epoch, self-resetting arrive ------
__device__ unsigned g_bar_arrive;          // zero-init; reset by last arriver
__device__ volatile unsigned g_bar_epoch;  // monotonic across replays

__device__ __forceinline__ void gsync() {
    __syncthreads();
    if (threadIdx.x == 0) {
        __threadfence();
        unsigned e = g_bar_epoch;
        if (atomicAdd(&g_bar_arrive, 1u) == gridDim.x - 1u) {
            g_bar_arrive = 0u;
            __threadfence();
            g_bar_epoch = e + 1u;
        } else {
            while (g_bar_epoch == e) { __nanosleep(64); }
        }
        __threadfence();
    }
    __syncthreads();
}

// ---------------- the whole model as one persistent kernel ----------------
__global__ void __launch_bounds__(NTH, 4) sage_fused(
    const float* __restrict__ x,     // [N,T]
    const float* __restrict__ convW, // [L,C,1,K]
    const float* __restrict__ convb, // [L,C]
    const float* __restrict__ alpha, // [L,T]
    const float* __restrict__ scale, // [L,T]
    const float* __restrict__ shift, // [L,T]
    const float* __restrict__ Wout,  // [3,N]
    const float* __restrict__ bout,  // [3]
    const int*   __restrict__ ei,    // [2,E]
    float*       __restrict__ out)   // [3]
{
    const int tid  = threadIdx.x;
    const int lane = tid & 31;
    const int w    = tid >> 5;
    const int b    = blockIdx.x;
    const int G    = gridDim.x;
    const int nthreads = G * NTH;
    const int gtid     = b * NTH + tid;
    const int nwarps   = G * 8;
    const int gwarp    = b * 8 + w;

    __shared__ float sh[8][64];
    __shared__ float sm[Tt], smul[Tt], ssh[Tt];
    __shared__ float sW[Cc * Kk];
    __shared__ float sbias[Cc];
    __shared__ float shp[8][3];

    // ---- P0: zero bucket cursors + accumulators ----
    for (int i = gtid; i < Nv; i += nthreads) g_cnt[i] = 0;
    if (b == 0) {
        if (tid < 64) { g_stat0[tid] = 0.f; g_stat1[tid] = 0.f; }
        if (tid < 3)  g_out3[tid] = 0.f;
    }
    gsync();  // S1

    // ---- P1: single-pass bucketed adjacency build + layer-0 column stats ----
    for (int e = gtid; e < Ee; e += nthreads * 4) {
        int ss[4], dd[4];
#pragma unroll
        for (int k = 0; k < 4; k++) {
            int idx = e + k * nthreads;
            if (idx < Ee) { ss[k] = ei[idx]; dd[k] = ei[Ee + idx]; }
            else          { dd[k] = -1; }
        }
#pragma unroll
        for (int k = 0; k < 4; k++) {
            if (dd[k] >= 0) {
                int slot = atomicAdd(&g_cnt[dd[k]], 1);
                if (slot < CAP) g_adj[dd[k] * CAP + slot] = ss[k];
            }
        }
    }
    {
        const int GSB = (G < 128) ? G : 128;
        if (b < GSB) {
            float s = 0.f, q = 0.f;
            for (int n = b * 8 + w; n < Nv; n += GSB * 8) {
                float v = x[n * Tt + lane];
                s += v; q = fmaf(v, v, q);
            }
            sh[w][lane] = s; sh[w][32 + lane] = q;
            __syncthreads();
            if (tid < 64) {
                float v = 0.f;
#pragma unroll
                for (int i = 0; i < 8; i++) v += sh[i][tid];
                atomicAdd(&g_stat0[tid], v);
            }
        }
    }
    gsync();  // S2

    // ---- P2: layer-0 stats finish (per block) + normconv-0 ----
    if (tid < Tt) {
        float s = g_stat0[tid], q = g_stat0[32 + tid];
        float m = s / (float)Nv;
        float a = alpha[tid];
        float nsq = q + (float)Nv * m * m * (a * a - 2.f * a);
        float invn = sqrtf((float)Nv) * rsqrtf(nsq);
        sm[tid]   = a * m;
        smul[tid] = invn * scale[tid];
        ssh[tid]  = shift[tid];
    }
    if (tid < Cc * Kk) sW[tid] = convW[tid];
    if (tid < Cc)      sbias[tid] = convb[tid];
    __syncthreads();
    for (int node = gwarp; node < Nv; node += nwarps) {
        float v = x[node * Tt + lane];
        v = fmaf(v - sm[lane], smul[lane], ssh[lane]);
        g_xn[node * Tt + lane] = v;
        float win[Kk];
#pragma unroll
        for (int d = -PADc; d <= PADc; d++) {
            int si = lane + d;
            float u = __shfl_sync(0xffffffffu, v, si & 31);
            win[d + PADc] = (si >= 0 && si < Tt) ? u : 0.f;
        }
        float mx = -3.0e38f;
#pragma unroll
        for (int c = 0; c < Cc; c++) {
            float a2 = sbias[c];
#pragma unroll
            for (int k = 0; k < Kk; k++) a2 = fmaf(win[k], sW[c * Kk + k], a2);
            mx = fmaxf(mx, a2);
        }
        g_cm[node * Tt + lane] = mx;
    }
    gsync();  // S3

    // ---- P3: aggr-0 (+relu) -> g_x, fused layer-1 stats accumulation ----
    {
        float s = 0.f, q = 0.f;
        for (int node = gwarp; node < Nv; node += nwarps) {
            int deg = g_cnt[node];
            if (deg > CAP) deg = CAP;
            const int base = node * CAP;
            float a0 = 0.f, a1 = 0.f, a2 = 0.f, a3 = 0.f;
            int i = 0;
            for (; i + 32 <= deg; i += 32) {
                int id = g_adj[base + i + lane];
#pragma unroll
                for (int j = 0; j < 32; j += 4) {
                    int s0 = __shfl_sync(0xffffffffu, id, j);
                    int s1 = __shfl_sync(0xffffffffu, id, j + 1);
                    int s2 = __shfl_sync(0xffffffffu, id, j + 2);
                    int s3 = __shfl_sync(0xffffffffu, id, j + 3);
                    a0 += g_cm[s0 * Tt + lane];
                    a1 += g_cm[s1 * Tt + lane];
                    a2 += g_cm[s2 * Tt + lane];
                    a3 += g_cm[s3 * Tt + lane];
                }
            }
            if (i < deg) {
                int id = (i + lane < deg) ? g_adj[base + i + lane] : 0;
                int m = deg - i;
                for (int j = 0; j < m; j++) {
                    int s0 = __shfl_sync(0xffffffffu, id, j);
                    a0 += g_cm[s0 * Tt + lane];
                }
            }
            float acc = (a0 + a1) + (a2 + a3);
            float invdeg = 1.0f / (float)(deg > 1 ? deg : 1);
            float v = fmaxf(0.5f * (g_xn[node * Tt + lane] + acc * invdeg), 0.f);
            g_x[node * Tt + lane] = v;
            s += v; q = fmaf(v, v, q);
        }
        sh[w][lane] = s; sh[w][32 + lane] = q;
        __syncthreads();
        if (tid < 64) {
            float v = 0.f;
#pragma unroll
            for (int i = 0; i < 8; i++) v += sh[i][tid];
            atomicAdd(&g_stat1[tid], v);
        }
    }
    gsync();  // S4

    // ---- P4: layer-1 stats finish + normconv-1 (src = g_x) ----
    if (tid < Tt) {
        float s = g_stat1[tid], q = g_stat1[32 + tid];
        float m = s / (float)Nv;
        float a = alpha[Tt + tid];
        float nsq = q + (float)Nv * m * m * (a * a - 2.f * a);
        float invn = sqrtf((float)Nv) * rsqrtf(nsq);
        sm[tid]   = a * m;
        smul[tid] = invn * scale[Tt + tid];
        ssh[tid]  = shift[Tt + tid];
    }
    if (tid < Cc * Kk) sW[tid] = convW[Cc * Kk + tid];
    if (tid < Cc)      sbias[tid] = convb[Cc + tid];
    __syncthreads();
    for (int node = gwarp; node < Nv; node += nwarps) {
        float v = g_x[node * Tt + lane];
        v = fmaf(v - sm[lane], smul[lane], ssh[lane]);
        g_xn[node * Tt + lane] = v;
        float win[Kk];
#pragma unroll
        for (int d = -PADc; d <= PADc; d++) {
            int si = lane + d;
            float u = __shfl_sync(0xffffffffu, v, si & 31);
            win[d + PADc] = (si >= 0 && si < Tt) ? u : 0.f;
        }
        float mx = -3.0e38f;
#pragma unroll
        for (int c = 0; c < Cc; c++) {
            float a2 = sbias[c];
#pragma unroll
            for (int k = 0; k < Kk; k++) a2 = fmaf(win[k], sW[c * Kk + k], a2);
            mx = fmaxf(mx, a2);
        }
        g_cm[node * Tt + lane] = mx;
    }
    gsync();  // S5

    // ---- P5: aggr-1 (+relu) fused with output head partials ----
    {
        float p0 = 0.f, p1 = 0.f, p2 = 0.f;
        for (int node = gwarp; node < Nv; node += nwarps) {
            int deg = g_cnt[node];
            if (deg > CAP) deg = CAP;
            const int base = node * CAP;
            float a0 = 0.f, a1 = 0.f, a2 = 0.f, a3 = 0.f;
            int i = 0;
            for (; i + 32 <= deg; i += 32) {
                int id = g_adj[base + i + lane];
#pragma unroll
                for (int j = 0; j < 32; j += 4) {
                    int s0 = __shfl_sync(0xffffffffu, id, j);
                    int s1 = __shfl_sync(0xffffffffu, id, j + 1);
                    int s2 = __shfl_sync(0xffffffffu, id, j + 2);
                    int s3 = __shfl_sync(0xffffffffu, id, j + 3);
                    a0 += g_cm[s0 * Tt + lane];
                    a1 += g_cm[s1 * Tt + lane];
                    a2 += g_cm[s2 * Tt + lane];
                    a3 += g_cm[s3 * Tt + lane];
                }
            }
            if (i < deg) {
                int id = (i + lane < deg) ? g_adj[base + i + lane] : 0;
                int m = deg - i;
                for (int j = 0; j < m; j++) {
                    int s0 = __shfl_sync(0xffffffffu, id, j);
                    a0 += g_cm[s0 * Tt + lane];
                }
            }
            float acc = (a0 + a1) + (a2 + a3);
            float invdeg = 1.0f / (float)(deg > 1 ? deg : 1);
            float v = fmaxf(0.5f * (g_xn[node * Tt + lane] + acc * invdeg), 0.f);
            float srow = v;
#pragma unroll
            for (int off = 16; off > 0; off >>= 1)
                srow += __shfl_down_sync(0xffffffffu, srow, off);
            if (lane == 0) {
                p0 = fmaf(Wout[node], srow, p0);
                p1 = fmaf(Wout[Nv + node], srow, p1);
                p2 = fmaf(Wout[2 * Nv + node], srow, p2);
            }
        }
        if (lane == 0) { shp[w][0] = p0; shp[w][1] = p1; shp[w][2] = p2; }
        __syncthreads();
        if (tid < 3) {
            float v = 0.f;
#pragma unroll
            for (int i = 0; i < 8; i++) v += shp[i][tid];
            atomicAdd(&g_out3[tid], v);
        }
    }
    gsync();  // S6

    // ---- P6: write the 3 logits ----
    if (b == 0 && tid < 3) out[tid] = g_out3[tid] + bout[tid];
}

// ---------------- launch ---------------------------------------------------
extern "C" void kernel_launch(void* const* d_in, const int* in_sizes, int n_in,
                              void* d_out, int out_size) {
    const float* x     = (const float*)d_in[0];
    const float* convW = (const float*)d_in[1];
    const float* convb = (const float*)d_in[2];
    const float* alpha = (const float*)d_in[3];
    const float* scale = (const float*)d_in[4];
    const float* shift = (const float*)d_in[5];
    const float* Wout  = (const float*)d_in[6];
    const float* bout  = (const float*)d_in[7];
    const int*   ei    = (const int*)d_in[8];
    float*       out   = (float*)d_out;

    int dev = 0;
    cudaGetDevice(&dev);
    int sms = 0;
    cudaDeviceGetAttribute(&sms, cudaDevAttrMultiProcessorCount, dev);
    int bpm = 0;
    cudaOccupancyMaxActiveBlocksPerMultiprocessor(&bpm, sage_fused, NTH, 0);
    if (bpm < 1) bpm = 1;
    int G = sms * bpm;
    if (G > MAXG) G = MAXG;

    void* args[10] = {
        (void*)&x, (void*)&convW, (void*)&convb, (void*)&alpha, (void*)&scale,
        (void*)&shift, (void*)&Wout, (void*)&bout, (void*)&ei, (void*)&out
    };
    cudaLaunchCooperativeKernel((const void*)sage_fused, dim3(G), dim3(NTH),
                                args, 0, (cudaStream_t)0);
}

// round 10
// speedup vs baseline: 4.6454x; 1.0242x over previous
#include <cuda_runtime.h>

// Problem constants
#define Nv    20000
#define Tt    32
#define Ee    640000
#define Cc    10
#define Kk    5
#define PADc  2
#define CAP   128      // bucket capacity per node (mean deg 32; P(>=128) ~ e^-81)
#define MAXG  512
#define NTH   256

// ---------------- static device scratch (no allocs allowed) ----------------
__device__ int   g_cnt[Nv];              // per-node degree / bucket cursor
__device__ int   g_adj[Nv * CAP];        // bucketed adjacency (src per dst)
__device__ float g_xn[Nv * Tt];          // normalized x of current layer
__device__ float g_cm[(Nv + 1) * Tt];    // per-node conv+max message (+zero row)
__device__ float g_x[Nv * Tt];           // layer-0 output
__device__ float g_stat0[64];            // layer-0 sum / sumsq per t
__device__ float g_stat1[64];            // layer-1 sum / sumsq per t
__device__ float g_out3[3];              // output partial sums

// -------- device-wide barrier: monotonic epoch, self-resetting arrive ------
__device__ unsigned g_bar_arrive;          // zero-init; reset by last arriver
__device__ volatile unsigned g_bar_epoch;  // monotonic across replays

__device__ __forceinline__ void gsync() {
    __syncthreads();
    if (threadIdx.x == 0) {
        __threadfence();
        unsigned e = g_bar_epoch;
        if (atomicAdd(&g_bar_arrive, 1u) == gridDim.x - 1u) {
            g_bar_arrive = 0u;
            __threadfence();
            g_bar_epoch = e + 1u;
        } else {
            while (g_bar_epoch == e) { __nanosleep(64); }
        }
        __threadfence();
    }
    __syncthreads();
}

// 8-chain padded gather over one node's bucket; returns neighbor sum for lane t
__device__ __forceinline__ float gather_row(int deg, int base, int lane) {
    float a0 = 0.f, a1 = 0.f, a2 = 0.f, a3 = 0.f;
    float a4 = 0.f, a5 = 0.f, a6 = 0.f, a7 = 0.f;
    for (int i = 0; i < deg; i += 32) {
        // pad out-of-range lanes with dummy node Nv (g_cm row Nv is all zeros)
        int id = (i + lane < deg) ? g_adj[base + i + lane] : Nv;
#pragma unroll
        for (int j = 0; j < 32; j += 8) {
            int s0 = __shfl_sync(0xffffffffu, id, j);
            int s1 = __shfl_sync(0xffffffffu, id, j + 1);
            int s2 = __shfl_sync(0xffffffffu, id, j + 2);
            int s3 = __shfl_sync(0xffffffffu, id, j + 3);
            int s4 = __shfl_sync(0xffffffffu, id, j + 4);
            int s5 = __shfl_sync(0xffffffffu, id, j + 5);
            int s6 = __shfl_sync(0xffffffffu, id, j + 6);
            int s7 = __shfl_sync(0xffffffffu, id, j + 7);
            a0 += g_cm[s0 * Tt + lane];
            a1 += g_cm[s1 * Tt + lane];
            a2 += g_cm[s2 * Tt + lane];
            a3 += g_cm[s3 * Tt + lane];
            a4 += g_cm[s4 * Tt + lane];
            a5 += g_cm[s5 * Tt + lane];
            a6 += g_cm[s6 * Tt + lane];
            a7 += g_cm[s7 * Tt + lane];
        }
    }
    return ((a0 + a1) + (a2 + a3)) + ((a4 + a5) + (a6 + a7));
}

// ---------------- the whole model as one persistent kernel ----------------
__global__ void __launch_bounds__(NTH, 4) sage_fused(
    const float* __restrict__ x,     // [N,T]
    const float* __restrict__ convW, // [L,C,1,K]
    const float* __restrict__ convb, // [L,C]
    const float* __restrict__ alpha, // [L,T]
    const float* __restrict__ scale, // [L,T]
    const float* __restrict__ shift, // [L,T]
    const float* __restrict__ Wout,  // [3,N]
    const float* __restrict__ bout,  // [3]
    const int*   __restrict__ ei,    // [2,E]
    float*       __restrict__ out)   // [3]
{
    const int tid  = threadIdx.x;
    const int lane = tid & 31;
    const int w    = tid >> 5;
    const int b    = blockIdx.x;
    const int G    = gridDim.x;
    const int nthreads = G * NTH;
    const int gtid     = b * NTH + tid;
    const int nwarps   = G * 8;
    const int gwarp    = b * 8 + w;

    __shared__ float sh[8][64];
    __shared__ float sm[Tt], smul[Tt], ssh[Tt];
    __shared__ float sW[Cc * Kk];
    __shared__ float sbias[Cc];
    __shared__ float shp[8][3];

    // ---- P0: zero bucket cursors + accumulators + dummy g_cm row ----
    for (int i = gtid; i < Nv; i += nthreads) g_cnt[i] = 0;
    if (b == 0) {
        if (tid < 64) { g_stat0[tid] = 0.f; g_stat1[tid] = 0.f; }
        if (tid < 3)  g_out3[tid] = 0.f;
        if (tid < Tt) g_cm[Nv * Tt + tid] = 0.f;  // zero padding row
    }
    gsync();  // S1

    // ---- P1: single-pass bucketed adjacency build + layer-0 column stats ----
    for (int e = gtid; e < Ee; e += nthreads * 4) {
        int ss[4], dd[4];
#pragma unroll
        for (int k = 0; k < 4; k++) {
            int idx = e + k * nthreads;
            if (idx < Ee) { ss[k] = ei[idx]; dd[k] = ei[Ee + idx]; }
            else          { dd[k] = -1; }
        }
#pragma unroll
        for (int k = 0; k < 4; k++) {
            if (dd[k] >= 0) {
                int slot = atomicAdd(&g_cnt[dd[k]], 1);
                if (slot < CAP) g_adj[dd[k] * CAP + slot] = ss[k];
            }
        }
    }
    {
        const int GSB = (G < 128) ? G : 128;
        if (b < GSB) {
            float s = 0.f, q = 0.f;
            for (int n = b * 8 + w; n < Nv; n += GSB * 8) {
                float v = x[n * Tt + lane];
                s += v; q = fmaf(v, v, q);
            }
            sh[w][lane] = s; sh[w][32 + lane] = q;
            __syncthreads();
            if (tid < 64) {
                float v = 0.f;
#pragma unroll
                for (int i = 0; i < 8; i++) v += sh[i][tid];
                atomicAdd(&g_stat0[tid], v);
            }
        }
    }
    gsync();  // S2

    // ---- P2: layer-0 stats finish (per block) + normconv-0 ----
    if (tid < Tt) {
        float s = g_stat0[tid], q = g_stat0[32 + tid];
        float m = s / (float)Nv;
        float a = alpha[tid];
        float nsq = q + (float)Nv * m * m * (a * a - 2.f * a);
        float invn = sqrtf((float)Nv) * rsqrtf(nsq);
        sm[tid]   = a * m;
        smul[tid] = invn * scale[tid];
        ssh[tid]  = shift[tid];
    }
    if (tid < Cc * Kk) sW[tid] = convW[tid];
    if (tid < Cc)      sbias[tid] = convb[tid];
    __syncthreads();
    for (int node = gwarp; node < Nv; node += nwarps) {
        float v = x[node * Tt + lane];
        v = fmaf(v - sm[lane], smul[lane], ssh[lane]);
        g_xn[node * Tt + lane] = v;
        float win[Kk];
#pragma unroll
        for (int d = -PADc; d <= PADc; d++) {
            int si = lane + d;
            float u = __shfl_sync(0xffffffffu, v, si & 31);
            win[d + PADc] = (si >= 0 && si < Tt) ? u : 0.f;
        }
        float mx = -3.0e38f;
#pragma unroll
        for (int c = 0; c < Cc; c++) {
            float a2 = sbias[c];
#pragma unroll
            for (int k = 0; k < Kk; k++) a2 = fmaf(win[k], sW[c * Kk + k], a2);
            mx = fmaxf(mx, a2);
        }
        g_cm[node * Tt + lane] = mx;
    }
    gsync();  // S3

    // ---- P3: aggr-0 (+relu) -> g_x, fused layer-1 stats accumulation ----
    {
        float s = 0.f, q = 0.f;
        for (int node = gwarp; node < Nv; node += nwarps) {
            int deg = g_cnt[node];
            if (deg > CAP) deg = CAP;
            float acc = gather_row(deg, node * CAP, lane);
            float invdeg = 1.0f / (float)(deg > 1 ? deg : 1);
            float v = fmaxf(0.5f * (g_xn[node * Tt + lane] + acc * invdeg), 0.f);
            g_x[node * Tt + lane] = v;
            s += v; q = fmaf(v, v, q);
        }
        sh[w][lane] = s; sh[w][32 + lane] = q;
        __syncthreads();
        if (tid < 64) {
            float v = 0.f;
#pragma unroll
            for (int i = 0; i < 8; i++) v += sh[i][tid];
            atomicAdd(&g_stat1[tid], v);
        }
    }
    gsync();  // S4

    // ---- P4: layer-1 stats finish + normconv-1 (src = g_x) ----
    if (tid < Tt) {
        float s = g_stat1[tid], q = g_stat1[32 + tid];
        float m = s / (float)Nv;
        float a = alpha[Tt + tid];
        float nsq = q + (float)Nv * m * m * (a * a - 2.f * a);
        float invn = sqrtf((float)Nv) * rsqrtf(nsq);
        sm[tid]   = a * m;
        smul[tid] = invn * scale[Tt + tid];
        ssh[tid]  = shift[Tt + tid];
    }
    if (tid < Cc * Kk) sW[tid] = convW[Cc * Kk + tid];
    if (tid < Cc)      sbias[tid] = convb[Cc + tid];
    __syncthreads();
    for (int node = gwarp; node < Nv; node += nwarps) {
        float v = g_x[node * Tt + lane];
        v = fmaf(v - sm[lane], smul[lane], ssh[lane]);
        g_xn[node * Tt + lane] = v;
        float win[Kk];
#pragma unroll
        for (int d = -PADc; d <= PADc; d++) {
            int si = lane + d;
            float u = __shfl_sync(0xffffffffu, v, si & 31);
            win[d + PADc] = (si >= 0 && si < Tt) ? u : 0.f;
        }
        float mx = -3.0e38f;
#pragma unroll
        for (int c = 0; c < Cc; c++) {
            float a2 = sbias[c];
#pragma unroll
            for (int k = 0; k < Kk; k++) a2 = fmaf(win[k], sW[c * Kk + k], a2);
            mx = fmaxf(mx, a2);
        }
        g_cm[node * Tt + lane] = mx;
    }
    gsync();  // S5

    // ---- P5: aggr-1 (+relu) fused with output head partials ----
    {
        float p0 = 0.f, p1 = 0.f, p2 = 0.f;
        for (int node = gwarp; node < Nv; node += nwarps) {
            int deg = g_cnt[node];
            if (deg > CAP) deg = CAP;
            float acc = gather_row(deg, node * CAP, lane);
            float invdeg = 1.0f / (float)(deg > 1 ? deg : 1);
            float v = fmaxf(0.5f * (g_xn[node * Tt + lane] + acc * invdeg), 0.f);
            float srow = v;
#pragma unroll
            for (int off = 16; off > 0; off >>= 1)
                srow += __shfl_down_sync(0xffffffffu, srow, off);
            if (lane == 0) {
                p0 = fmaf(Wout[node], srow, p0);
                p1 = fmaf(Wout[Nv + node], srow, p1);
                p2 = fmaf(Wout[2 * Nv + node], srow, p2);
            }
        }
        if (lane == 0) { shp[w][0] = p0; shp[w][1] = p1; shp[w][2] = p2; }
        __syncthreads();
        if (tid < 3) {
            float v = 0.f;
#pragma unroll
            for (int i = 0; i < 8; i++) v += shp[i][tid];
            atomicAdd(&g_out3[tid], v);
        }
    }
    gsync();  // S6

    // ---- P6: write the 3 logits ----
    if (b == 0 && tid < 3) out[tid] = g_out3[tid] + bout[tid];
}

// ---------------- launch ---------------------------------------------------
extern "C" void kernel_launch(void* const* d_in, const int* in_sizes, int n_in,
                              void* d_out, int out_size) {
    const float* x     = (const float*)d_in[0];
    const float* convW = (const float*)d_in[1];
    const float* convb = (const float*)d_in[2];
    const float* alpha = (const float*)d_in[3];
    const float* scale = (const float*)d_in[4];
    const float* shift = (const float*)d_in[5];
    const float* Wout  = (const float*)d_in[6];
    const float* bout  = (const float*)d_in[7];
    const int*   ei    = (const int*)d_in[8];
    float*       out   = (float*)d_out;

    int dev = 0;
    cudaGetDevice(&dev);
    int sms = 0;
    cudaDeviceGetAttribute(&sms, cudaDevAttrMultiProcessorCount, dev);
    int bpm = 0;
    cudaOccupancyMaxActiveBlocksPerMultiprocessor(&bpm, sage_fused, NTH, 0);
    if (bpm < 1) bpm = 1;
    int G = sms * bpm;
    if (G > MAXG) G = MAXG;

    void* args[10] = {
        (void*)&x, (void*)&convW, (void*)&convb, (void*)&alpha, (void*)&scale,
        (void*)&shift, (void*)&Wout, (void*)&bout, (void*)&ei, (void*)&out
    };
    cudaLaunchCooperativeKernel((const void*)sage_fused, dim3(G), dim3(NTH),
                                args, 0, (cudaStream_t)0);
}

// round 11
// speedup vs baseline: 4.7988x; 1.0330x over previous
#include <cuda_runtime.h>

// Problem constants
#define Nv    20000
#define Tt    32
#define Ee    640000
#define Cc    10
#define Kk    5
#define PADc  2
#define CAP   128      // bucket capacity per node (mean deg 32; P(>=128) ~ e^-81)
#define MAXG  512
#define NTH   256
#define NUNITS 5000    // Nv/4 work units (4 nodes per warp per unit)

// ---------------- static device scratch (no allocs allowed) ----------------
__device__ int   g_cnt[Nv];              // per-node degree / bucket cursor
__device__ int   g_adj[Nv * CAP];        // bucketed adjacency (src per dst)
__device__ float g_xn[Nv * Tt];          // normalized x of current layer
__device__ float g_cm[(Nv + 1) * Tt];    // per-node conv+max message (+zero row)
__device__ float g_x[Nv * Tt];           // layer-0 output
__device__ float g_stat0[64];            // layer-0 sum / sumsq per t
__device__ float g_stat1[64];            // layer-1 sum / sumsq per t
__device__ float g_out3[3];              // output partial sums
__device__ int   g_ctrA, g_ctrB;         // work-steal counters (aggr phases)

// -------- device-wide barrier: monotonic epoch, self-resetting arrive ------
__device__ unsigned g_bar_arrive;          // zero-init; reset by last arriver
__device__ volatile unsigned g_bar_epoch;  // monotonic across replays

__device__ __forceinline__ void gsync() {
    __syncthreads();
    if (threadIdx.x == 0) {
        __threadfence();
        unsigned e = g_bar_epoch;
        if (atomicAdd(&g_bar_arrive, 1u) == gridDim.x - 1u) {
            g_bar_arrive = 0u;
            __threadfence();
            g_bar_epoch = e + 1u;
        } else {
            while (g_bar_epoch == e) { __nanosleep(64); }
        }
        __threadfence();
    }
    __syncthreads();
}

// float4 group-gather: 8 lanes per node, lane covers t = sub*4 .. sub*4+3.
// Per 4 edges: 1 int4 id load + 4 independent float4 gathers. No shuffles.
__device__ __forceinline__ float4 gather4(int deg, int base, int sub) {
    float4 A = make_float4(0.f, 0.f, 0.f, 0.f);
    float4 B = make_float4(0.f, 0.f, 0.f, 0.f);
    const int kfull = deg & ~3;
    for (int k = 0; k < kfull; k += 4) {
        int4 id4 = *(const int4*)&g_adj[base + k];
        const float4 v0 = *(const float4*)&g_cm[id4.x * Tt + sub * 4];
        const float4 v1 = *(const float4*)&g_cm[id4.y * Tt + sub * 4];
        const float4 v2 = *(const float4*)&g_cm[id4.z * Tt + sub * 4];
        const float4 v3 = *(const float4*)&g_cm[id4.w * Tt + sub * 4];
        A.x += v0.x + v1.x;  B.x += v2.x + v3.x;
        A.y += v0.y + v1.y;  B.y += v2.y + v3.y;
        A.z += v0.z + v1.z;  B.z += v2.z + v3.z;
        A.w += v0.w + v1.w;  B.w += v2.w + v3.w;
    }
    if (deg & 3) {
        int4 id4 = *(const int4*)&g_adj[base + kfull];
        int i0 = (kfull + 0 < deg) ? id4.x : Nv;  // row Nv is all zeros
        int i1 = (kfull + 1 < deg) ? id4.y : Nv;
        int i2 = (kfull + 2 < deg) ? id4.z : Nv;
        int i3 = (kfull + 3 < deg) ? id4.w : Nv;
        const float4 v0 = *(const float4*)&g_cm[i0 * Tt + sub * 4];
        const float4 v1 = *(const float4*)&g_cm[i1 * Tt + sub * 4];
        const float4 v2 = *(const float4*)&g_cm[i2 * Tt + sub * 4];
        const float4 v3 = *(const float4*)&g_cm[i3 * Tt + sub * 4];
        A.x += v0.x + v1.x;  B.x += v2.x + v3.x;
        A.y += v0.y + v1.y;  B.y += v2.y + v3.y;
        A.z += v0.z + v1.z;  B.z += v2.z + v3.z;
        A.w += v0.w + v1.w;  B.w += v2.w + v3.w;
    }
    return make_float4(A.x + B.x, A.y + B.y, A.z + B.z, A.w + B.w);
}

// ---------------- the whole model as one persistent kernel ----------------
__global__ void __launch_bounds__(NTH, 4) sage_fused(
    const float* __restrict__ x,     // [N,T]
    const float* __restrict__ convW, // [L,C,1,K]
    const float* __restrict__ convb, // [L,C]
    const float* __restrict__ alpha, // [L,T]
    const float* __restrict__ scale, // [L,T]
    const float* __restrict__ shift, // [L,T]
    const float* __restrict__ Wout,  // [3,N]
    const float* __restrict__ bout,  // [3]
    const int*   __restrict__ ei,    // [2,E]
    float*       __restrict__ out)   // [3]
{
    const int tid  = threadIdx.x;
    const int lane = tid & 31;
    const int w    = tid >> 5;
    const int sub  = lane & 7;   // position within 8-lane node group
    const int grp  = lane >> 3;  // node group 0..3 within warp
    const int b    = blockIdx.x;
    const int G    = gridDim.x;
    const int nthreads = G * NTH;
    const int gtid     = b * NTH + tid;
    const int nwarps   = G * 8;
    const int gwarp    = b * 8 + w;

    __shared__ float sh[8][64];
    __shared__ float sm[Tt], smul[Tt], ssh[Tt];
    __shared__ float sW[Cc * Kk];
    __shared__ float sbias[Cc];
    __shared__ float shp[8][3];

    // ---- P0: zero bucket cursors + accumulators + counters + dummy row ----
    for (int i = gtid; i < Nv; i += nthreads) g_cnt[i] = 0;
    if (b == 0) {
        if (tid < 64) { g_stat0[tid] = 0.f; g_stat1[tid] = 0.f; }
        if (tid < 3)  g_out3[tid] = 0.f;
        if (tid < Tt) g_cm[Nv * Tt + tid] = 0.f;  // zero padding row
        if (tid == 0) { g_ctrA = 0; g_ctrB = 0; }
    }
    gsync();  // S1

    // ---- P1: single-pass bucketed adjacency build + layer-0 column stats ----
    for (int e = gtid; e < Ee; e += nthreads * 4) {
        int ss[4], dd[4];
#pragma unroll
        for (int k = 0; k < 4; k++) {
            int idx = e + k * nthreads;
            if (idx < Ee) { ss[k] = ei[idx]; dd[k] = ei[Ee + idx]; }
            else          { dd[k] = -1; }
        }
#pragma unroll
        for (int k = 0; k < 4; k++) {
            if (dd[k] >= 0) {
                int slot = atomicAdd(&g_cnt[dd[k]], 1);
                if (slot < CAP) g_adj[dd[k] * CAP + slot] = ss[k];
            }
        }
    }
    {
        const int GSB = (G < 128) ? G : 128;
        if (b < GSB) {
            float s = 0.f, q = 0.f;
            for (int n = b * 8 + w; n < Nv; n += GSB * 8) {
                float v = x[n * Tt + lane];
                s += v; q = fmaf(v, v, q);
            }
            sh[w][lane] = s; sh[w][32 + lane] = q;
            __syncthreads();
            if (tid < 64) {
                float v = 0.f;
#pragma unroll
                for (int i = 0; i < 8; i++) v += sh[i][tid];
                atomicAdd(&g_stat0[tid], v);
            }
        }
    }
    gsync();  // S2

    // ---- P2: layer-0 stats finish (per block) + normconv-0 ----
    if (tid < Tt) {
        float s = g_stat0[tid], q = g_stat0[32 + tid];
        float m = s / (float)Nv;
        float a = alpha[tid];
        float nsq = q + (float)Nv * m * m * (a * a - 2.f * a);
        float invn = sqrtf((float)Nv) * rsqrtf(nsq);
        sm[tid]   = a * m;
        smul[tid] = invn * scale[tid];
        ssh[tid]  = shift[tid];
    }
    if (tid < Cc * Kk) sW[tid] = convW[tid];
    if (tid < Cc)      sbias[tid] = convb[tid];
    __syncthreads();
    for (int node = gwarp; node < Nv; node += nwarps) {
        float v = x[node * Tt + lane];
        v = fmaf(v - sm[lane], smul[lane], ssh[lane]);
        g_xn[node * Tt + lane] = v;
        float win[Kk];
#pragma unroll
        for (int d = -PADc; d <= PADc; d++) {
            int si = lane + d;
            float u = __shfl_sync(0xffffffffu, v, si & 31);
            win[d + PADc] = (si >= 0 && si < Tt) ? u : 0.f;
        }
        float mx = -3.0e38f;
#pragma unroll
        for (int c = 0; c < Cc; c++) {
            float a2 = sbias[c];
#pragma unroll
            for (int k = 0; k < Kk; k++) a2 = fmaf(win[k], sW[c * Kk + k], a2);
            mx = fmaxf(mx, a2);
        }
        g_cm[node * Tt + lane] = mx;
    }
    gsync();  // S3

    // ---- P3: aggr-0 (+relu) -> g_x, fused layer-1 stats (work-stealing) ----
    {
        float4 s4 = make_float4(0.f, 0.f, 0.f, 0.f);
        float4 q4 = make_float4(0.f, 0.f, 0.f, 0.f);
        for (;;) {
            int nb;
            if (lane == 0) nb = atomicAdd(&g_ctrA, 1);
            nb = __shfl_sync(0xffffffffu, nb, 0);
            if (nb >= NUNITS) break;
            const int node = nb * 4 + grp;
            int deg = g_cnt[node];
            if (deg > CAP) deg = CAP;
            float4 acc = gather4(deg, node * CAP, sub);
            const float inv = 1.0f / (float)(deg > 1 ? deg : 1);
            const float4 xn = *(const float4*)&g_xn[node * Tt + sub * 4];
            float4 v;
            v.x = fmaxf(0.5f * fmaf(acc.x, inv, xn.x), 0.f);
            v.y = fmaxf(0.5f * fmaf(acc.y, inv, xn.y), 0.f);
            v.z = fmaxf(0.5f * fmaf(acc.z, inv, xn.z), 0.f);
            v.w = fmaxf(0.5f * fmaf(acc.w, inv, xn.w), 0.f);
            *(float4*)&g_x[node * Tt + sub * 4] = v;
            s4.x += v.x; q4.x = fmaf(v.x, v.x, q4.x);
            s4.y += v.y; q4.y = fmaf(v.y, v.y, q4.y);
            s4.z += v.z; q4.z = fmaf(v.z, v.z, q4.z);
            s4.w += v.w; q4.w = fmaf(v.w, v.w, q4.w);
        }
        // reduce across the 4 groups (lanes with equal sub share t-range)
#pragma unroll
        for (int off = 8; off < 32; off <<= 1) {
            s4.x += __shfl_xor_sync(0xffffffffu, s4.x, off);
            s4.y += __shfl_xor_sync(0xffffffffu, s4.y, off);
            s4.z += __shfl_xor_sync(0xffffffffu, s4.z, off);
            s4.w += __shfl_xor_sync(0xffffffffu, s4.w, off);
            q4.x += __shfl_xor_sync(0xffffffffu, q4.x, off);
            q4.y += __shfl_xor_sync(0xffffffffu, q4.y, off);
            q4.z += __shfl_xor_sync(0xffffffffu, q4.z, off);
            q4.w += __shfl_xor_sync(0xffffffffu, q4.w, off);
        }
        if (lane < 8) {
            sh[w][lane * 4 + 0] = s4.x;  sh[w][32 + lane * 4 + 0] = q4.x;
            sh[w][lane * 4 + 1] = s4.y;  sh[w][32 + lane * 4 + 1] = q4.y;
            sh[w][lane * 4 + 2] = s4.z;  sh[w][32 + lane * 4 + 2] = q4.z;
            sh[w][lane * 4 + 3] = s4.w;  sh[w][32 + lane * 4 + 3] = q4.w;
        }
        __syncthreads();
        if (tid < 64) {
            float v = 0.f;
#pragma unroll
            for (int i = 0; i < 8; i++) v += sh[i][tid];
            atomicAdd(&g_stat1[tid], v);
        }
    }
    gsync();  // S4

    // ---- P4: layer-1 stats finish + normconv-1 (src = g_x) ----
    if (tid < Tt) {
        float s = g_stat1[tid], q = g_stat1[32 + tid];
        float m = s / (float)Nv;
        float a = alpha[Tt + tid];
        float nsq = q + (float)Nv * m * m * (a * a - 2.f * a);
        float invn = sqrtf((float)Nv) * rsqrtf(nsq);
        sm[tid]   = a * m;
        smul[tid] = invn * scale[Tt + tid];
        ssh[tid]  = shift[Tt + tid];
    }
    if (tid < Cc * Kk) sW[tid] = convW[Cc * Kk + tid];
    if (tid < Cc)      sbias[tid] = convb[Cc + tid];
    __syncthreads();
    for (int node = gwarp; node < Nv; node += nwarps) {
        float v = g_x[node * Tt + lane];
        v = fmaf(v - sm[lane], smul[lane], ssh[lane]);
        g_xn[node * Tt + lane] = v;
        float win[Kk];
#pragma unroll
        for (int d = -PADc; d <= PADc; d++) {
            int si = lane + d;
            float u = __shfl_sync(0xffffffffu, v, si & 31);
            win[d + PADc] = (si >= 0 && si < Tt) ? u : 0.f;
        }
        float mx = -3.0e38f;
#pragma unroll
        for (int c = 0; c < Cc; c++) {
            float a2 = sbias[c];
#pragma unroll
            for (int k = 0; k < Kk; k++) a2 = fmaf(win[k], sW[c * Kk + k], a2);
            mx = fmaxf(mx, a2);
        }
        g_cm[node * Tt + lane] = mx;
    }
    gsync();  // S5

    // ---- P5: aggr-1 (+relu) + output head partials (work-stealing) ----
    {
        float p0 = 0.f, p1 = 0.f, p2 = 0.f;
        for (;;) {
            int nb;
            if (lane == 0) nb = atomicAdd(&g_ctrB, 1);
            nb = __shfl_sync(0xffffffffu, nb, 0);
            if (nb >= NUNITS) break;
            const int node = nb * 4 + grp;
            int deg = g_cnt[node];
            if (deg > CAP) deg = CAP;
            float4 acc = gather4(deg, node * CAP, sub);
            const float inv = 1.0f / (float)(deg > 1 ? deg : 1);
            const float4 xn = *(const float4*)&g_xn[node * Tt + sub * 4];
            float rs = fmaxf(0.5f * fmaf(acc.x, inv, xn.x), 0.f)
                     + fmaxf(0.5f * fmaf(acc.y, inv, xn.y), 0.f)
                     + fmaxf(0.5f * fmaf(acc.z, inv, xn.z), 0.f)
                     + fmaxf(0.5f * fmaf(acc.w, inv, xn.w), 0.f);
            // rowsum within the 8-lane group
            rs += __shfl_xor_sync(0xffffffffu, rs, 1);
            rs += __shfl_xor_sync(0xffffffffu, rs, 2);
            rs += __shfl_xor_sync(0xffffffffu, rs, 4);
            if (sub == 0) {
                p0 = fmaf(Wout[node], rs, p0);
                p1 = fmaf(Wout[Nv + node], rs, p1);
                p2 = fmaf(Wout[2 * Nv + node], rs, p2);
            }
        }
        // sum the 4 group-leader lanes (others hold 0)
#pragma unroll
        for (int off = 8; off < 32; off <<= 1) {
            p0 += __shfl_xor_sync(0xffffffffu, p0, off);
            p1 += __shfl_xor_sync(0xffffffffu, p1, off);
            p2 += __shfl_xor_sync(0xffffffffu, p2, off);
        }
        if (lane == 0) { shp[w][0] = p0; shp[w][1] = p1; shp[w][2] = p2; }
        __syncthreads();
        if (tid < 3) {
            float v = 0.f;
#pragma unroll
            for (int i = 0; i < 8; i++) v += shp[i][tid];
            atomicAdd(&g_out3[tid], v);
        }
    }
    gsync();  // S6

    // ---- P6: write the 3 logits ----
    if (b == 0 && tid < 3) out[tid] = g_out3[tid] + bout[tid];
}

// ---------------- launch ---------------------------------------------------
extern "C" void kernel_launch(void* const* d_in, const int* in_sizes, int n_in,
                              void* d_out, int out_size) {
    const float* x     = (const float*)d_in[0];
    const float* convW = (const float*)d_in[1];
    const float* convb = (const float*)d_in[2];
    const float* alpha = (const float*)d_in[3];
    const float* scale = (const float*)d_in[4];
    const float* shift = (const float*)d_in[5];
    const float* Wout  = (const float*)d_in[6];
    const float* bout  = (const float*)d_in[7];
    const int*   ei    = (const int*)d_in[8];
    float*       out   = (float*)d_out;

    int dev = 0;
    cudaGetDevice(&dev);
    int sms = 0;
    cudaDeviceGetAttribute(&sms, cudaDevAttrMultiProcessorCount, dev);
    int bpm = 0;
    cudaOccupancyMaxActiveBlocksPerMultiprocessor(&bpm, sage_fused, NTH, 0);
    if (bpm < 1) bpm = 1;
    int G = sms * bpm;
    if (G > MAXG) G = MAXG;

    void* args[10] = {
        (void*)&x, (void*)&convW, (void*)&convb, (void*)&alpha, (void*)&scale,
        (void*)&shift, (void*)&Wout, (void*)&bout, (void*)&ei, (void*)&out
    };
    cudaLaunchCooperativeKernel((const void*)sage_fused, dim3(G), dim3(NTH),
                                args, 0, (cudaStream_t)0);
}